// round 14
// baseline (speedup 1.0000x reference)
#include <cuda_runtime.h>
#include <math.h>

// Problem constants
#define BATCH 16
#define LROWS 192   // 6*L rows of raw
#define AC    2046  // attributor columns
#define MC    2048  // M = A + 2
#define LD    32    // L (W_2 output dim)
#define TCOL  256   // column slots per block
#define NCB   8     // col-blocks (8*256 = 2048 slots: 2046 cols + 2 specials)

// Scratch (device globals; no allocation allowed)
__device__ float g_pS[BATCH][NCB][2][64];  // partial S per (batch, col-block)
__device__ int   g_ctr[BATCH];             // self-resetting finisher counters (init 0)

// ---------------------------------------------------------------------------
// Single fused kernel. grid (cb=8, b=16) = 128 blocks x 512 threads (16 warps).
// Prologue: issue phase-1 iter-0 streaming loads FIRST (registers), then all
// misc loads (user/item, W2[0:128] transposed into smem, adj/iw packing);
// the wq/wk fold's dependent chain hides under the in-flight streaming loads.
// Phase 1: warps 0-7 Q rows, 8-15 K rows, row-major 1KB spans.
// Causal once; V phase folds into partial S via shfl; partials to g_pS.
// Last-of-8 block per batch reduces + projects + writes out (plain stores).
// ---------------------------------------------------------------------------
__global__ __launch_bounds__(512) void main_kernel(
    const float* __restrict__ user, const float* __restrict__ item,
    const float* __restrict__ attributor, const float* __restrict__ W1,
    const float* __restrict__ W2,
    const float* __restrict__ adj, const float* __restrict__ iw,
    float* __restrict__ out) {

    __shared__ __align__(16) float hpool[8 * 2 * TCOL]; // 4096: W2t alias -> Q partials
    __shared__ __align__(16) float kpool[8 * 2 * TCOL]; // 4096: K partials -> W2e (finisher)
    __shared__ float c_sh[2][TCOL];
    __shared__ float aA[2][TCOL], aP[2][TCOL], aR[2][TCOL];
    __shared__ float wqs[128], wks[128];   // [n*64+j]
    __shared__ float usit[2 * LROWS];      // user rows then item rows
    __shared__ float qsks[2][2][32];       // [n][q/k][l]
    __shared__ float Ssum[128];
    __shared__ int fin;

    int b  = blockIdx.y;
    int cb = blockIdx.x;
    int t  = threadIdx.x;
    int w  = t >> 5;
    int l  = t & 31;
    int c0 = cb * TCOL;
    bool lastcb = (cb == NCB - 1);

    float* W2t = hpool;   // W2t[l*128 + row] = W2[row*32 + l], rows 0..127

    // ---- prefetch phase-1 iteration 0 (issued before everything else) ----
    int qk = w >> 3;                 // 0: Q warps, 1: K warps
    int wr = w & 7;
    int r0q = qk * 64 + wr * 8;
    float2 avp[2][4], wvp[2][4];
    #pragma unroll
    for (int rr = 0; rr < 2; rr++) {
        const float* ap = attributor + ((size_t)(b * LROWS + r0q + rr)) * AC + c0 + 2 * l;
        const float* wp = W1 + ((size_t)(r0q + rr)) * AC + c0 + 2 * l;
        #pragma unroll
        for (int k = 0; k < 4; k++) {
            bool sp = lastcb && (l == 31) && (k == 3);
            avp[rr][k] = sp ? make_float2(0.f, 0.f) : *(const float2*)(ap + 64 * k);
            wvp[rr][k] = sp ? make_float2(0.f, 0.f) : *(const float2*)(wp + 64 * k);
        }
    }

    // ---- prologue misc loads (independent, issued in one batch) ----
    if (t < LROWS)            usit[t] = user[b * LROWS + t];
    else if (t < 2 * LROWS)   usit[t] = item[b * LROWS + (t - LROWS)];
    {
        // stage W2 rows 0..127 transposed: W2t[l*128+row]
        float4 wa = *(const float4*)(W2 + t * 8);
        float4 wb = *(const float4*)(W2 + t * 8 + 4);
        float tmp[8] = {wa.x, wa.y, wa.z, wa.w, wb.x, wb.y, wb.z, wb.w};
        #pragma unroll
        for (int e = 0; e < 8; e++) {
            int idx = t * 8 + e;
            W2t[(idx & 31) * 128 + (idx >> 5)] = tmp[e];
        }
    }
    {
        // adj/iw packing for this block's 256 slots
        int n = t >> 8, c = t & 255;
        int m = c0 + c + 1;
        if (lastcb && c == 254) m = 0;
        else if (lastcb && c == 255) m = MC - 1;
        int coln = n ? (MC - 1) : 0;
        float a = adj[(size_t)m * MC + coln];
        aA[n][c] = a;
        aP[n][c] = a * iw[(size_t)m * MC + coln];
        aR[n][c] = adj[(size_t)coln * MC + m] * iw[(size_t)coln * MC + m];
    }
    __syncthreads();

    // ---- fold 1: qs/ks (bank-conflict-free via rotated j) ----
    if (t < 128) {
        int n = t >> 6, qq = (t >> 5) & 1, ll = t & 31;
        float s = 0.f;
        #pragma unroll
        for (int jj = 0; jj < 64; jj++) {
            int j = (ll + jj) & 63;
            float x = fmaxf(usit[n * LROWS + qq * 64 + j], 0.f);
            s = fmaf(x, W2t[ll * 128 + qq * 64 + j], s);
        }
        qsks[n][qq][ll] = s;
    }
    __syncthreads();

    // ---- fold 2: wq/wk ----
    if (t < 256) {
        int n = t >> 7, sel = (t >> 6) & 1, j = t & 63;
        float s = 0.f;
        if (sel == 0) {
            #pragma unroll
            for (int ll = 0; ll < 32; ll++)
                s = fmaf(W2t[ll * 128 + j], qsks[n][1][ll], s);
            wqs[n * 64 + j] = s;
        } else {
            #pragma unroll
            for (int ll = 0; ll < 32; ll++)
                s = fmaf(W2t[ll * 128 + 64 + j], qsks[n][0][ll], s);
            wks[n * 64 + j] = s;
        }
    }
    __syncthreads();   // W2t (hpool) dead from here; hpool reused for Q partials

    // ---- phase 1: Q/K row streaming ----
    {
        const float* wsel = qk ? wks : wqs;
        float acc[4][4];
        #pragma unroll
        for (int k = 0; k < 4; k++)
            acc[k][0] = acc[k][1] = acc[k][2] = acc[k][3] = 0.f;

        #pragma unroll
        for (int itr = 0; itr < 4; itr++) {
            int r = r0q + itr * 2;
            float2 av[2][4], wv[2][4];
            if (itr == 0) {
                #pragma unroll
                for (int rr = 0; rr < 2; rr++)
                    #pragma unroll
                    for (int k = 0; k < 4; k++) { av[rr][k] = avp[rr][k]; wv[rr][k] = wvp[rr][k]; }
            } else {
                #pragma unroll
                for (int rr = 0; rr < 2; rr++) {
                    const float* ap = attributor + ((size_t)(b * LROWS + r + rr)) * AC + c0 + 2 * l;
                    const float* wp = W1 + ((size_t)(r + rr)) * AC + c0 + 2 * l;
                    #pragma unroll
                    for (int k = 0; k < 4; k++) {
                        bool sp = lastcb && (l == 31) && (k == 3);
                        av[rr][k] = sp ? make_float2(0.f, 0.f) : *(const float2*)(ap + 64 * k);
                        wv[rr][k] = sp ? make_float2(0.f, 0.f) : *(const float2*)(wp + 64 * k);
                    }
                }
            }
            #pragma unroll
            for (int rr = 0; rr < 2; rr++) {
                int rg = r + rr;
                int j  = wr * 8 + itr * 2 + rr;
                float w0 = wsel[j], w1 = wsel[64 + j];
                #pragma unroll
                for (int k = 0; k < 4; k++) {
                    float x0, x1;
                    if (lastcb && (l == 31) && (k == 3)) {
                        x0 = fmaxf(usit[rg], 0.f);           // user node (m=0)
                        x1 = fmaxf(usit[LROWS + rg], 0.f);   // item node (m=2047)
                    } else {
                        x0 = fmaxf(av[rr][k].x * wv[rr][k].x, 0.f);
                        x1 = fmaxf(av[rr][k].y * wv[rr][k].y, 0.f);
                    }
                    acc[k][0] = fmaf(x0, w0, acc[k][0]);
                    acc[k][1] = fmaf(x0, w1, acc[k][1]);
                    acc[k][2] = fmaf(x1, w0, acc[k][2]);
                    acc[k][3] = fmaf(x1, w1, acc[k][3]);
                }
            }
        }
        float* dst = (qk ? kpool : hpool) + wr * (2 * TCOL);
        #pragma unroll
        for (int k = 0; k < 4; k++) {
            int c = 64 * k + 2 * l;
            dst[c]            = acc[k][0];
            dst[TCOL + c]     = acc[k][1];
            dst[c + 1]        = acc[k][2];
            dst[TCOL + c + 1] = acc[k][3];
        }
    }
    __syncthreads();

    // ---- causal ----
    {
        int n = t >> 8, c = t & 255;
        float hq = 0.f, hk = 0.f;
        #pragma unroll
        for (int w8 = 0; w8 < 8; w8++) {
            hq += hpool[w8 * (2 * TCOL) + n * TCOL + c];
            hk += kpool[w8 * (2 * TCOL) + n * TCOL + c];
        }
        float d = hq * aP[n][c] - hk * aR[n][c];
        c_sh[n][c] = aA[n][c] / (1.0f + expf(-d));
    }
    __syncthreads();

    // ---- V phase: fold into partial S, write g_pS ----
    {
        int vr0 = 128 + w * 4;
        #pragma unroll
        for (int itr = 0; itr < 2; itr++) {
            int r = vr0 + itr * 2;
            float2 av[2][4], wv[2][4];
            #pragma unroll
            for (int rr = 0; rr < 2; rr++) {
                const float* ap = attributor + ((size_t)(b * LROWS + r + rr)) * AC + c0 + 2 * l;
                const float* wp = W1 + ((size_t)(r + rr)) * AC + c0 + 2 * l;
                #pragma unroll
                for (int k = 0; k < 4; k++) {
                    bool sp = lastcb && (l == 31) && (k == 3);
                    av[rr][k] = sp ? make_float2(0.f, 0.f) : *(const float2*)(ap + 64 * k);
                    wv[rr][k] = sp ? make_float2(0.f, 0.f) : *(const float2*)(wp + 64 * k);
                }
            }
            #pragma unroll
            for (int rr = 0; rr < 2; rr++) {
                int rg = r + rr;
                int j  = rg - 128;
                float v0 = 0.f, v1 = 0.f;
                #pragma unroll
                for (int k = 0; k < 4; k++) {
                    float x0, x1;
                    if (lastcb && (l == 31) && (k == 3)) {
                        x0 = fmaxf(usit[rg], 0.f);
                        x1 = fmaxf(usit[LROWS + rg], 0.f);
                    } else {
                        x0 = fmaxf(av[rr][k].x * wv[rr][k].x, 0.f);
                        x1 = fmaxf(av[rr][k].y * wv[rr][k].y, 0.f);
                    }
                    int c = 64 * k + 2 * l;
                    v0 = fmaf(x0, c_sh[0][c], v0);
                    v0 = fmaf(x1, c_sh[0][c + 1], v0);
                    v1 = fmaf(x0, c_sh[1][c], v1);
                    v1 = fmaf(x1, c_sh[1][c + 1], v1);
                }
                #pragma unroll
                for (int off = 16; off; off >>= 1) {
                    v0 += __shfl_xor_sync(0xffffffffu, v0, off);
                    v1 += __shfl_xor_sync(0xffffffffu, v1, off);
                }
                if (l == 0) {
                    g_pS[b][cb][0][j] = v0;
                    g_pS[b][cb][1][j] = v1;
                }
            }
        }
        if (l == 0) __threadfence();   // make this warp's g_pS stores visible
    }
    __syncthreads();

    // ---- finisher election (self-resetting counter) ----
    if (t == 0) {
        int v = atomicAdd(&g_ctr[b], 1);
        fin = (v == NCB - 1);
        if (v == NCB - 1) g_ctr[b] = 0;   // reset for next launch
    }
    __syncthreads();

    if (fin) {
        // stage W2 rows 128..191 into kpool (dead), reduce partials, project
        #pragma unroll
        for (int i = 0; i < 4; i++)
            kpool[t + 512 * i] = W2[128 * LD + t + 512 * i];
        if (t < 128) {
            int n = t >> 6, j = t & 63;
            float s = 0.f;
            #pragma unroll
            for (int q = 0; q < NCB; q++)
                s += __ldcg(&g_pS[b][q][n][j]);
            Ssum[t] = s;
        }
        __syncthreads();
        if (t < 64) {
            int ll = t >> 1, n = t & 1;
            float s = 0.f;
            #pragma unroll
            for (int j = 0; j < 64; j++)
                s = fmaf(kpool[j * LD + ll], Ssum[n * 64 + j], s);
            out[b * 64 + ll * 2 + n] = s;   // plain store: no zeroing needed
        }
    }
}

extern "C" void kernel_launch(void* const* d_in, const int* in_sizes, int n_in,
                              void* d_out, int out_size) {
    const float* user       = (const float*)d_in[0];
    const float* item       = (const float*)d_in[1];
    const float* attributor = (const float*)d_in[2];
    const float* adj        = (const float*)d_in[3];
    const float* iw         = (const float*)d_in[4];
    const float* W1         = (const float*)d_in[5];
    const float* W2         = (const float*)d_in[6];
    float* out = (float*)d_out;

    main_kernel<<<dim3(NCB, BATCH), 512>>>(user, item, attributor, W1, W2, adj, iw, out);
}